// round 1
// baseline (speedup 1.0000x reference)
#include <cuda_runtime.h>

// Problem constants (fixed by the reference: B,T,E hardcoded, L = T//2)
#define BB 32
#define TT 4096
#define EE 256
#define LL 2048

// Scratch (allocation-free rule: __device__ globals)
__device__ int g_src[BB * LL];   // g_src[b*LL + r] = source token index of r-th kept row
__device__ int g_cnt[BB];        // kept count per batch

// ---------------------------------------------------------------------------
// K1: per-batch exclusive scan of keep mask over the first LL tokens.
// keep = (x[b,t,0] * (1+|p|)) < 0  ⟺  x[b,t,0] < 0   (scale is strictly positive)
// One block per batch, 256 threads, 8 tokens/thread.
// ---------------------------------------------------------------------------
__global__ void scan_kernel(const float* __restrict__ x) {
    const int b   = blockIdx.x;
    const int tid = threadIdx.x;          // 0..255
    const int PER = LL / 256;             // 8
    const int base = tid * PER;
    const float* xb = x + (size_t)b * TT * EE;

    unsigned mask = 0;
    int cnt = 0;
#pragma unroll
    for (int i = 0; i < PER; i++) {
        float v = xb[(size_t)(base + i) * EE];   // channel 0
        if (v < 0.0f) { mask |= (1u << i); cnt++; }
    }

    __shared__ int s[256];
    s[tid] = cnt;
    __syncthreads();
    // Hillis-Steele inclusive scan over 256 partial counts
#pragma unroll
    for (int off = 1; off < 256; off <<= 1) {
        int v = (tid >= off) ? s[tid - off] : 0;
        __syncthreads();
        s[tid] += v;
        __syncthreads();
    }
    int excl = s[tid] - cnt;
    if (tid == 255) g_cnt[b] = s[255];

    int* dst = g_src + b * LL;
#pragma unroll
    for (int i = 0; i < PER; i++) {
        if (mask & (1u << i)) dst[excl++] = base + i;
    }
}

// ---------------------------------------------------------------------------
// K2: gather. One 256-thread block handles 4 output rows; each row is copied
// by 64 lanes as float4 (1 KB row -> 64 x 16 B, fully coalesced read+write).
// Row r < cnt[b]: copy source row, scaling channel 0.
// Row r >= cnt[b]: zeros (base is zeros; THRESHOLD = 0).
// ---------------------------------------------------------------------------
__global__ void gather_kernel(const float* __restrict__ x,
                              const float* __restrict__ pamt,
                              float* __restrict__ out) {
    const int tid    = threadIdx.x;
    const int row_in = tid >> 6;          // 0..3
    const int lane   = tid & 63;          // 0..63
    const int gr     = blockIdx.x * 4 + row_in;   // global output row in [0, BB*LL)
    const int b      = gr / LL;
    const int r      = gr - b * LL;

    float4* orow = (float4*)(out + (size_t)gr * EE);
    const int cnt = g_cnt[b];

    if (r < cnt) {
        const int src = g_src[b * LL + r];
        const float4* xrow = (const float4*)(x + ((size_t)b * TT + src) * EE);
        float4 v = xrow[lane];
        if (lane == 0) {
            float scale = 1.0f + fabsf(pamt[0]);
            v.x *= scale;
        }
        orow[lane] = v;
    } else {
        orow[lane] = make_float4(0.0f, 0.0f, 0.0f, 0.0f);
    }
}

// ---------------------------------------------------------------------------
extern "C" void kernel_launch(void* const* d_in, const int* in_sizes, int n_in,
                              void* d_out, int out_size) {
    const float* x    = (const float*)d_in[0];   // (32, 4096, 256) f32
    const float* pamt = (const float*)d_in[1];   // (1,) f32
    // d_in[2] = clipped_length (scalar, always T//2 = 2048; geometry is compile-time)
    float* out = (float*)d_out;                  // (32, 2048, 256) f32

    scan_kernel<<<BB, 256>>>(x);
    gather_kernel<<<(BB * LL) / 4, 256>>>(x, pamt, out);
}

// round 2
// speedup vs baseline: 1.3303x; 1.3303x over previous
#include <cuda_runtime.h>

// Problem constants (fixed by the reference: B,T,E hardcoded, L = T//2)
#define BB 32
#define TT 4096
#define EE 256
#define LL 2048

// Scratch (allocation-free rule: __device__ globals)
__device__ int g_src[BB * LL];   // g_src[b*LL + r] = source token of r-th kept row
__device__ int g_cnt[BB];        // kept count per batch

// ---------------------------------------------------------------------------
// K1: per-batch exclusive scan of keep mask over the first LL tokens.
// keep = (x[b,t,0] * (1+|p|)) < 0  ⟺  x[b,t,0] < 0   (scale strictly positive)
// One block per batch, 1024 threads, 2 tokens/thread, shuffle warp-scan.
// ---------------------------------------------------------------------------
__global__ __launch_bounds__(1024) void scan_kernel(const float* __restrict__ x) {
    const int b    = blockIdx.x;
    const int tid  = threadIdx.x;            // 0..1023
    const int lane = tid & 31;
    const int wid  = tid >> 5;               // 0..31
    const float* xb = x + (size_t)b * TT * EE;
    const int base = tid * 2;

    const float v0 = xb[(size_t)base * EE];
    const float v1 = xb[(size_t)(base + 1) * EE];
    const int k0 = (v0 < 0.0f);
    const int k1 = (v1 < 0.0f);
    const int cnt = k0 + k1;

    // warp inclusive scan of per-thread counts
    int s = cnt;
#pragma unroll
    for (int o = 1; o < 32; o <<= 1) {
        int t = __shfl_up_sync(0xffffffffu, s, o);
        if (lane >= o) s += t;
    }

    __shared__ int wsum[32];
    if (lane == 31) wsum[wid] = s;
    __syncthreads();

    if (wid == 0) {
        int t  = wsum[lane];
        int ss = t;
#pragma unroll
        for (int o = 1; o < 32; o <<= 1) {
            int u = __shfl_up_sync(0xffffffffu, ss, o);
            if (lane >= o) ss += u;
        }
        wsum[lane] = ss - t;                 // exclusive warp offset
        if (lane == 31) g_cnt[b] = ss;       // inclusive total
    }
    __syncthreads();

    int excl = wsum[wid] + (s - cnt);        // exclusive prefix for this thread
    int* dst = g_src + b * LL;
    if (k0) dst[excl++] = base;
    if (k1) dst[excl]   = base + 1;
}

// ---------------------------------------------------------------------------
// K2: gather. One warp per output row: 32 lanes x 2 float4 = 1 KB row,
// fully coalesced both sides. Streaming stores (.cs) keep x resident in L2
// across graph replays (x = 128 MB vs 126 MB L2; out writes would evict it).
// Row r <  cnt[b]: copy source row, scale channel 0.
// Row r >= cnt[b]: zeros (base zeros, THRESHOLD = 0).
// ---------------------------------------------------------------------------
__global__ __launch_bounds__(256) void gather_kernel(const float* __restrict__ x,
                                                     const float* __restrict__ pamt,
                                                     float* __restrict__ out) {
    const int wid  = threadIdx.x >> 5;            // 0..7
    const int lane = threadIdx.x & 31;
    const int gr   = blockIdx.x * 8 + wid;        // global output row [0, BB*LL)
    const int b    = gr >> 11;                    // / LL (2048)
    const int r    = gr & (LL - 1);

    float4* orow = (float4*)(out + (size_t)gr * EE);
    const int cnt = g_cnt[b];

    if (r < cnt) {
        const int src = g_src[gr];                // b*LL + r == gr
        const float4* xrow = (const float4*)(x + ((size_t)b * TT + src) * EE);
        float4 a = xrow[lane];
        float4 c = xrow[lane + 32];
        if (lane == 0) a.x *= (1.0f + fabsf(__ldg(pamt)));
        __stcs(orow + lane,      a);
        __stcs(orow + lane + 32, c);
    } else {
        const float4 z = make_float4(0.0f, 0.0f, 0.0f, 0.0f);
        __stcs(orow + lane,      z);
        __stcs(orow + lane + 32, z);
    }
}

// ---------------------------------------------------------------------------
extern "C" void kernel_launch(void* const* d_in, const int* in_sizes, int n_in,
                              void* d_out, int out_size) {
    const float* x    = (const float*)d_in[0];   // (32, 4096, 256) f32
    const float* pamt = (const float*)d_in[1];   // (1,) f32
    // d_in[2] = clipped_length (always T//2 = 2048; geometry compile-time)
    float* out = (float*)d_out;                  // (32, 2048, 256) f32

    scan_kernel<<<BB, 1024>>>(x);
    gather_kernel<<<(BB * LL) / 8, 256>>>(x, pamt, out);
}